// round 3
// baseline (speedup 1.0000x reference)
#include <cuda_runtime.h>
#include <cuda_bf16.h>
#include <math.h>

// ---------------------------------------------------------------------------
// SwinV2 block, fp32 baseline.
// B=8, C=192, H=W=128, HEADS=6, WS=8, SHIFT=4, N=64, HIDDEN=768
// Token count TOK = 131072. Windows per image 256, total windows 2048.
// ---------------------------------------------------------------------------

#define TOK   131072
#define CCH   192
#define HEADS 6
#define HDIM  32
#define NWIN  2048      // B * 256
#define HID   768

// scratch (device globals; allocation-free per harness rules)
__device__ float g_xw  [ (size_t)TOK * CCH ];    // LN1 + shifted-window gather, [t][192]; reused as xn2
__device__ float g_qkv [ (size_t)TOK * 576 ];    // [t][576]
__device__ float g_ao  [ (size_t)TOK * CCH ];    // attention out, [t][192]
__device__ float g_x1  [ (size_t)TOK * CCH ];    // residual-1 in NHWC [p][192]
__device__ float g_h   [ (size_t)TOK * HID ];    // MLP hidden [p][768]
__device__ float g_table [ 225 * HEADS ];        // CPB-MLP table
__device__ float g_rpbias[ HEADS * 64 * 64 ];    // 16*sigmoid(rpb)

// ---------------------------------------------------------------------------
// CPB MLP: 225 rel positions -> 512 relu -> 6 heads
// ---------------------------------------------------------------------------
__device__ __forceinline__ float relcoord(int ci) {
    float v = (float)(ci - 7) * (8.0f / 7.0f);
    float r = log2f(fabsf(v) + 1.0f) * (1.0f / 3.0f);   // log2(8)=3
    return (v < 0.0f) ? -r : r;
}

__global__ void cpb_table_kernel(const float* __restrict__ w1,
                                 const float* __restrict__ b1,
                                 const float* __restrict__ w2) {
    __shared__ float hid[512];
    int pos = blockIdx.x;                 // 0..224
    int a = pos / 15, b = pos % 15;
    float r0 = relcoord(a), r1 = relcoord(b);
    int u = threadIdx.x;                  // 512 threads
    hid[u] = fmaxf(0.0f, r0 * w1[2 * u] + r1 * w1[2 * u + 1] + b1[u]);
    __syncthreads();
    int warp = u >> 5, lane = u & 31;
    if (warp < HEADS) {
        float s = 0.0f;
        #pragma unroll
        for (int k = 0; k < 16; k++) {
            int uu = lane + (k << 5);
            s += hid[uu] * w2[warp * 512 + uu];
        }
        #pragma unroll
        for (int off = 16; off > 0; off >>= 1)
            s += __shfl_xor_sync(0xffffffffu, s, off);
        if (lane == 0) g_table[pos * HEADS + warp] = s;
    }
}

__global__ void rpbias_kernel() {
    int e = blockIdx.x * blockDim.x + threadIdx.x;   // < 24576
    int h = e >> 12;
    int rem = e & 4095;
    int i = rem >> 6, j = rem & 63;
    int d0 = (i >> 3) - (j >> 3) + 7;
    int d1 = (i & 7) - (j & 7) + 7;
    float t = g_table[(d0 * 15 + d1) * HEADS + h];
    g_rpbias[e] = 16.0f / (1.0f + expf(-t));
}

// ---------------------------------------------------------------------------
// LN1 + cyclic shift + window partition.  32 tokens/block, 192 threads.
// ---------------------------------------------------------------------------
__global__ void ln1_kernel(const float* __restrict__ x,
                           const float* __restrict__ nw,
                           const float* __restrict__ nb) {
    __shared__ float s[32][193];
    __shared__ float smu[32], srs[32];
    int tid = threadIdx.x;
    int t0 = blockIdx.x << 5;

    for (int e = tid; e < 32 * 192; e += 192) {
        int tk = e & 31;
        int c  = e >> 5;
        int t  = t0 + tk;
        int win = t >> 6, n = t & 63;
        int b = win >> 8, wi = win & 255;
        int h = ((((wi >> 4) << 3) + (n >> 3)) + 4) & 127;
        int w = ((((wi & 15) << 3) + (n & 7)) + 4) & 127;
        s[tk][c] = x[(((size_t)b * CCH + c) << 14) + (h << 7) + w];
    }
    __syncthreads();
    if (tid < 32) {
        float sum = 0.0f, sq = 0.0f;
        #pragma unroll 4
        for (int c = 0; c < 192; c++) { float v = s[tid][c]; sum += v; sq += v * v; }
        float mu = sum * (1.0f / 192.0f);
        float var = sq * (1.0f / 192.0f) - mu * mu;
        smu[tid] = mu;
        srs[tid] = rsqrtf(var + 1e-5f);
    }
    __syncthreads();
    int c = tid;                   // 0..191
    float wv = nw[c], bv = nb[c];
    #pragma unroll 4
    for (int tk = 0; tk < 32; tk++) {
        g_xw[(size_t)(t0 + tk) * CCH + c] = (s[tk][c] - smu[tk]) * srs[tk] * wv + bv;
    }
}

// ---------------------------------------------------------------------------
// LN2 over x1 (NHWC [p][192]); warp per row; output into g_xw (reuse).
// ---------------------------------------------------------------------------
__global__ void ln2_kernel(const float* __restrict__ nw,
                           const float* __restrict__ nb) {
    int warp = threadIdx.x >> 5, lane = threadIdx.x & 31;
    int p = (blockIdx.x << 3) + warp;
    const float* row = g_x1 + (size_t)p * CCH;
    float v[6];
    float sum = 0.0f, sq = 0.0f;
    #pragma unroll
    for (int k = 0; k < 6; k++) {
        v[k] = row[lane + (k << 5)];
        sum += v[k]; sq += v[k] * v[k];
    }
    #pragma unroll
    for (int off = 16; off > 0; off >>= 1) {
        sum += __shfl_xor_sync(0xffffffffu, sum, off);
        sq  += __shfl_xor_sync(0xffffffffu, sq,  off);
    }
    float mu = sum * (1.0f / 192.0f);
    float rstd = rsqrtf(sq * (1.0f / 192.0f) - mu * mu + 1e-5f);
    float* out = g_xw + (size_t)p * CCH;
    #pragma unroll
    for (int k = 0; k < 6; k++) {
        int c = lane + (k << 5);
        out[c] = (v[k] - mu) * rstd * nw[c] + nb[c];
    }
}

// ---------------------------------------------------------------------------
// Attention per (head, window). grid (6, 2048), 128 threads.
// ---------------------------------------------------------------------------
__device__ __forceinline__ int swin_region(int v) {
    return (v < 120) ? 0 : ((v < 124) ? 1 : 2);
}

__global__ void attn_kernel(const float* __restrict__ logit_scale) {
    __shared__ __align__(16) float sq[64][36];
    __shared__ __align__(16) float sk[64][36];
    __shared__ __align__(16) float sv[64][36];
    __shared__ float sS[64][65];
    __shared__ int sreg[64];

    int head = blockIdx.x;
    int wg   = blockIdx.y;
    int tid  = threadIdx.x;
    int t0   = wg << 6;
    int wi   = wg & 255;
    int wh   = wi >> 4, ww = wi & 15;

    for (int e = tid; e < 2048; e += 128) {
        int n = e >> 5, d = e & 31;
        size_t g = (size_t)(t0 + n) * 576 + (head << 5) + d;
        sq[n][d] = g_qkv[g];
        sk[n][d] = g_qkv[g + 192];
        sv[n][d] = g_qkv[g + 384];
    }
    __syncthreads();

    float ls = expf(fminf(logit_scale[head], 4.6051701859880914f)); // ln(100)

    if (tid < 64) {
        int r = tid;
        float s = 0.0f;
        #pragma unroll
        for (int d = 0; d < 32; d++) s += sq[r][d] * sq[r][d];
        float sc = ls / fmaxf(sqrtf(s), 1e-12f);
        #pragma unroll
        for (int d = 0; d < 32; d++) sq[r][d] *= sc;
        int hs = (wh << 3) + (r >> 3);
        int ws_ = (ww << 3) + (r & 7);
        sreg[r] = 3 * swin_region(hs) + swin_region(ws_);
    } else {
        int r = tid - 64;
        float s = 0.0f;
        #pragma unroll
        for (int d = 0; d < 32; d++) s += sk[r][d] * sk[r][d];
        float sc = 1.0f / fmaxf(sqrtf(s), 1e-12f);
        #pragma unroll
        for (int d = 0; d < 32; d++) sk[r][d] *= sc;
    }
    __syncthreads();

    // S = qn kn^T + bias + mask
    #pragma unroll 1
    for (int it = 0; it < 32; it++) {
        int s = tid + (it << 7);
        int i = s >> 6, j = s & 63;
        const float4* qv = (const float4*)sq[i];
        const float4* kv = (const float4*)sk[j];
        float acc = 0.0f;
        #pragma unroll
        for (int d = 0; d < 8; d++) {
            float4 a = qv[d], b = kv[d];
            acc += a.x * b.x + a.y * b.y + a.z * b.z + a.w * b.w;
        }
        acc += g_rpbias[(head << 12) + (i << 6) + j];
        if (sreg[i] != sreg[j]) acc -= 100.0f;
        sS[i][j] = acc;
    }
    __syncthreads();

    // softmax per row
    if (tid < 64) {
        int r = tid;
        float m = -1e30f;
        #pragma unroll 4
        for (int j = 0; j < 64; j++) m = fmaxf(m, sS[r][j]);
        float sum = 0.0f;
        #pragma unroll 4
        for (int j = 0; j < 64; j++) { float e = expf(sS[r][j] - m); sS[r][j] = e; sum += e; }
        float inv = 1.0f / sum;
        #pragma unroll 4
        for (int j = 0; j < 64; j++) sS[r][j] *= inv;
    }
    __syncthreads();

    // O = P @ V
    #pragma unroll 1
    for (int it = 0; it < 16; it++) {
        int e = tid + (it << 7);
        int i = e >> 5, d = e & 31;
        float acc = 0.0f;
        #pragma unroll
        for (int j = 0; j < 64; j++) acc += sS[i][j] * sv[j][d];
        g_ao[(size_t)(t0 + i) * CCH + (head << 5) + d] = acc;
    }
}

// ---------------------------------------------------------------------------
// Generic fp32 GEMM: out[M x NC] = A[M x K] @ W[NC x K]^T  (+ epilogue)
// BM=128, BN=64, BK=32, 256 threads, 8x4 micro-tile, reg prefetch.
// MODE 0: qkv   (A=g_xw,  K=192, NC=576)  + q/v bias           -> g_qkv
// MODE 1: proj  (A=g_ao,  K=192, NC=192)  + bias + residual    -> g_x1 (NHWC)
// MODE 2: fc1   (A=g_xw,  K=192, NC=768)  + bias + gelu        -> g_h
// MODE 3: fc2   (A=g_h,   K=768, NC=192)  + bias + x1 residual -> d_out (NCHW)
// ---------------------------------------------------------------------------
template <int MODE>
__global__ void __launch_bounds__(256) gemm_kernel(const float* __restrict__ W,
                                                   const float* __restrict__ bias,
                                                   const float* __restrict__ bias2,
                                                   const float* __restrict__ aux,
                                                   float* __restrict__ outext) {
    constexpr int K  = (MODE == 3) ? 768 : 192;
    constexpr int NK = K >> 5;

    const float* A = (MODE == 0 || MODE == 2) ? g_xw : (MODE == 1 ? g_ao : g_h);

    __shared__ __align__(16) float As[128][36];
    __shared__ __align__(16) float Bs[32][68];

    int tid = threadIdx.x;
    int m0 = blockIdx.y << 7;
    int o0 = blockIdx.x << 6;
    const float* Ab = A + (size_t)m0 * K;
    const float* Wb = W + (size_t)o0 * K;

    int ar = tid >> 3;            // 0..31
    int ac = (tid & 7) << 2;      // 0,4,...,28

    float4 pa[4], pb[2];
    #pragma unroll
    for (int p = 0; p < 4; p++)
        pa[p] = *(const float4*)&Ab[(size_t)(ar + (p << 5)) * K + ac];
    #pragma unroll
    for (int p = 0; p < 2; p++)
        pb[p] = *(const float4*)&Wb[(size_t)(ar + (p << 5)) * K + ac];

    float acc[8][4];
    #pragma unroll
    for (int r = 0; r < 8; r++)
        #pragma unroll
        for (int j = 0; j < 4; j++) acc[r][j] = 0.0f;

    int tr = tid >> 4;            // 0..15 -> 8 rows
    int tc = tid & 15;            // 0..15 -> 4 cols

    #pragma unroll 1
    for (int kt = 0; kt < NK; kt++) {
        #pragma unroll
        for (int p = 0; p < 4; p++)
            *(float4*)&As[ar + (p << 5)][ac] = pa[p];
        #pragma unroll
        for (int p = 0; p < 2; p++) {
            int br = ar + (p << 5);
            Bs[ac + 0][br] = pb[p].x;
            Bs[ac + 1][br] = pb[p].y;
            Bs[ac + 2][br] = pb[p].z;
            Bs[ac + 3][br] = pb[p].w;
        }
        __syncthreads();
        if (kt + 1 < NK) {
            int k0 = (kt + 1) << 5;
            #pragma unroll
            for (int p = 0; p < 4; p++)
                pa[p] = *(const float4*)&Ab[(size_t)(ar + (p << 5)) * K + k0 + ac];
            #pragma unroll
            for (int p = 0; p < 2; p++)
                pb[p] = *(const float4*)&Wb[(size_t)(ar + (p << 5)) * K + k0 + ac];
        }
        #pragma unroll
        for (int k = 0; k < 32; k++) {
            float4 bv = *(const float4*)&Bs[k][tc << 2];
            #pragma unroll
            for (int r = 0; r < 8; r++) {
                float a = As[(tr << 3) + r][k];
                acc[r][0] += a * bv.x;
                acc[r][1] += a * bv.y;
                acc[r][2] += a * bv.z;
                acc[r][3] += a * bv.w;
            }
        }
        __syncthreads();
    }

    #pragma unroll
    for (int r = 0; r < 8; r++) {
        int m = m0 + (tr << 3) + r;
        #pragma unroll
        for (int j = 0; j < 4; j++) {
            int o = o0 + (tc << 2) + j;
            float v = acc[r][j];
            if constexpr (MODE == 0) {
                if (o < 192) v += bias[o];
                else if (o >= 384) v += bias2[o - 384];
                g_qkv[(size_t)m * 576 + o] = v;
            } else if constexpr (MODE == 1) {
                v += bias[o];
                int win = m >> 6, n = m & 63;
                int b = win >> 8, wi = win & 255;
                int h = ((((wi >> 4) << 3) + (n >> 3)) + 4) & 127;
                int w = ((((wi & 15) << 3) + (n & 7)) + 4) & 127;
                v += aux[(((size_t)b * CCH + o) << 14) + (h << 7) + w];
                g_x1[(size_t)((b << 14) + (h << 7) + w) * CCH + o] = v;
            } else if constexpr (MODE == 2) {
                v += bias[o];
                v = 0.5f * v * (1.0f + erff(v * 0.70710678118654752f));
                g_h[(size_t)m * HID + o] = v;
            } else {
                v += bias[o] + g_x1[(size_t)m * CCH + o];
                int b = m >> 14, hw = m & 16383;
                outext[(((size_t)b * CCH + o) << 14) + hw] = v;
            }
        }
    }
}

// ---------------------------------------------------------------------------
extern "C" void kernel_launch(void* const* d_in, const int* in_sizes, int n_in,
                              void* d_out, int out_size) {
    const float* x        = (const float*)d_in[0];
    const float* norm1_w  = (const float*)d_in[1];
    const float* norm1_b  = (const float*)d_in[2];
    const float* qkv_w    = (const float*)d_in[3];
    const float* q_bias   = (const float*)d_in[4];
    const float* v_bias   = (const float*)d_in[5];
    const float* logit_sc = (const float*)d_in[6];
    const float* cpb_w1   = (const float*)d_in[7];
    const float* cpb_b1   = (const float*)d_in[8];
    const float* cpb_w2   = (const float*)d_in[9];
    const float* proj_w   = (const float*)d_in[10];
    const float* proj_b   = (const float*)d_in[11];
    const float* norm2_w  = (const float*)d_in[12];
    const float* norm2_b  = (const float*)d_in[13];
    const float* fc1_w    = (const float*)d_in[14];
    const float* fc1_b    = (const float*)d_in[15];
    const float* fc2_w    = (const float*)d_in[16];
    const float* fc2_b    = (const float*)d_in[17];
    float* out = (float*)d_out;

    cpb_table_kernel<<<225, 512>>>(cpb_w1, cpb_b1, cpb_w2);
    rpbias_kernel<<<96, 256>>>();
    ln1_kernel<<<TOK / 32, 192>>>(x, norm1_w, norm1_b);
    gemm_kernel<0><<<dim3(9, TOK / 128), 256>>>(qkv_w, q_bias, v_bias, nullptr, nullptr);
    attn_kernel<<<dim3(HEADS, NWIN), 128>>>(logit_sc);
    gemm_kernel<1><<<dim3(3, TOK / 128), 256>>>(proj_w, proj_b, nullptr, x, nullptr);
    ln2_kernel<<<TOK / 8, 256>>>(norm2_w, norm2_b);
    gemm_kernel<2><<<dim3(12, TOK / 128), 256>>>(fc1_w, fc1_b, nullptr, nullptr, nullptr);
    gemm_kernel<3><<<dim3(3, TOK / 128), 256>>>(fc2_w, fc2_b, nullptr, nullptr, out);
}

// round 4
// speedup vs baseline: 1.9138x; 1.9138x over previous
#include <cuda_runtime.h>
#include <cuda_bf16.h>
#include <math.h>

// ---------------------------------------------------------------------------
// SwinV2 block. Round 3: all four GEMMs on tensor cores (tf32 mma.sync).
// B=8, C=192, H=W=128, HEADS=6, WS=8, SHIFT=4, N=64, HIDDEN=768
// ---------------------------------------------------------------------------

#define TOK   131072
#define CCH   192
#define HEADS 6
#define HDIM  32
#define NWIN  2048
#define HID   768

__device__ float g_xw  [ (size_t)TOK * CCH ];
__device__ float g_qkv [ (size_t)TOK * 576 ];
__device__ float g_ao  [ (size_t)TOK * CCH ];
__device__ float g_x1  [ (size_t)TOK * CCH ];
__device__ float g_h   [ (size_t)TOK * HID ];
__device__ float g_table [ 225 * HEADS ];
__device__ float g_rpbias[ HEADS * 64 * 64 ];

// ---------------------------------------------------------------------------
__device__ __forceinline__ float relcoord(int ci) {
    float v = (float)(ci - 7) * (8.0f / 7.0f);
    float r = log2f(fabsf(v) + 1.0f) * (1.0f / 3.0f);
    return (v < 0.0f) ? -r : r;
}

__global__ void cpb_table_kernel(const float* __restrict__ w1,
                                 const float* __restrict__ b1,
                                 const float* __restrict__ w2) {
    __shared__ float hid[512];
    int pos = blockIdx.x;
    int a = pos / 15, b = pos % 15;
    float r0 = relcoord(a), r1 = relcoord(b);
    int u = threadIdx.x;
    hid[u] = fmaxf(0.0f, r0 * w1[2 * u] + r1 * w1[2 * u + 1] + b1[u]);
    __syncthreads();
    int warp = u >> 5, lane = u & 31;
    if (warp < HEADS) {
        float s = 0.0f;
        #pragma unroll
        for (int k = 0; k < 16; k++) {
            int uu = lane + (k << 5);
            s += hid[uu] * w2[warp * 512 + uu];
        }
        #pragma unroll
        for (int off = 16; off > 0; off >>= 1)
            s += __shfl_xor_sync(0xffffffffu, s, off);
        if (lane == 0) g_table[pos * HEADS + warp] = s;
    }
}

__global__ void rpbias_kernel() {
    int e = blockIdx.x * blockDim.x + threadIdx.x;
    int h = e >> 12;
    int rem = e & 4095;
    int i = rem >> 6, j = rem & 63;
    int d0 = (i >> 3) - (j >> 3) + 7;
    int d1 = (i & 7) - (j & 7) + 7;
    float t = g_table[(d0 * 15 + d1) * HEADS + h];
    g_rpbias[e] = 16.0f / (1.0f + expf(-t));
}

// ---------------------------------------------------------------------------
__global__ void ln1_kernel(const float* __restrict__ x,
                           const float* __restrict__ nw,
                           const float* __restrict__ nb) {
    __shared__ float s[32][193];
    __shared__ float smu[32], srs[32];
    int tid = threadIdx.x;
    int t0 = blockIdx.x << 5;

    for (int e = tid; e < 32 * 192; e += 192) {
        int tk = e & 31;
        int c  = e >> 5;
        int t  = t0 + tk;
        int win = t >> 6, n = t & 63;
        int b = win >> 8, wi = win & 255;
        int h = ((((wi >> 4) << 3) + (n >> 3)) + 4) & 127;
        int w = ((((wi & 15) << 3) + (n & 7)) + 4) & 127;
        s[tk][c] = x[(((size_t)b * CCH + c) << 14) + (h << 7) + w];
    }
    __syncthreads();
    if (tid < 32) {
        float sum = 0.0f, sq = 0.0f;
        #pragma unroll 4
        for (int c = 0; c < 192; c++) { float v = s[tid][c]; sum += v; sq += v * v; }
        float mu = sum * (1.0f / 192.0f);
        float var = sq * (1.0f / 192.0f) - mu * mu;
        smu[tid] = mu;
        srs[tid] = rsqrtf(var + 1e-5f);
    }
    __syncthreads();
    int c = tid;
    float wv = nw[c], bv = nb[c];
    #pragma unroll 4
    for (int tk = 0; tk < 32; tk++) {
        g_xw[(size_t)(t0 + tk) * CCH + c] = (s[tk][c] - smu[tk]) * srs[tk] * wv + bv;
    }
}

__global__ void ln2_kernel(const float* __restrict__ nw,
                           const float* __restrict__ nb) {
    int warp = threadIdx.x >> 5, lane = threadIdx.x & 31;
    int p = (blockIdx.x << 3) + warp;
    const float* row = g_x1 + (size_t)p * CCH;
    float v[6];
    float sum = 0.0f, sq = 0.0f;
    #pragma unroll
    for (int k = 0; k < 6; k++) {
        v[k] = row[lane + (k << 5)];
        sum += v[k]; sq += v[k] * v[k];
    }
    #pragma unroll
    for (int off = 16; off > 0; off >>= 1) {
        sum += __shfl_xor_sync(0xffffffffu, sum, off);
        sq  += __shfl_xor_sync(0xffffffffu, sq,  off);
    }
    float mu = sum * (1.0f / 192.0f);
    float rstd = rsqrtf(sq * (1.0f / 192.0f) - mu * mu + 1e-5f);
    float* out = g_xw + (size_t)p * CCH;
    #pragma unroll
    for (int k = 0; k < 6; k++) {
        int c = lane + (k << 5);
        out[c] = (v[k] - mu) * rstd * nw[c] + nb[c];
    }
}

// ---------------------------------------------------------------------------
__device__ __forceinline__ int swin_region(int v) {
    return (v < 120) ? 0 : ((v < 124) ? 1 : 2);
}

__global__ void attn_kernel(const float* __restrict__ logit_scale) {
    __shared__ __align__(16) float sq[64][36];
    __shared__ __align__(16) float sk[64][36];
    __shared__ __align__(16) float sv[64][36];
    __shared__ float sS[64][65];
    __shared__ int sreg[64];

    int head = blockIdx.x;
    int wg   = blockIdx.y;
    int tid  = threadIdx.x;
    int t0   = wg << 6;
    int wi   = wg & 255;
    int wh   = wi >> 4, ww = wi & 15;

    for (int e = tid; e < 2048; e += 128) {
        int n = e >> 5, d = e & 31;
        size_t g = (size_t)(t0 + n) * 576 + (head << 5) + d;
        sq[n][d] = g_qkv[g];
        sk[n][d] = g_qkv[g + 192];
        sv[n][d] = g_qkv[g + 384];
    }
    __syncthreads();

    float ls = expf(fminf(logit_scale[head], 4.6051701859880914f));

    if (tid < 64) {
        int r = tid;
        float s = 0.0f;
        #pragma unroll
        for (int d = 0; d < 32; d++) s += sq[r][d] * sq[r][d];
        float sc = ls / fmaxf(sqrtf(s), 1e-12f);
        #pragma unroll
        for (int d = 0; d < 32; d++) sq[r][d] *= sc;
        int hs = (wh << 3) + (r >> 3);
        int ws_ = (ww << 3) + (r & 7);
        sreg[r] = 3 * swin_region(hs) + swin_region(ws_);
    } else {
        int r = tid - 64;
        float s = 0.0f;
        #pragma unroll
        for (int d = 0; d < 32; d++) s += sk[r][d] * sk[r][d];
        float sc = 1.0f / fmaxf(sqrtf(s), 1e-12f);
        #pragma unroll
        for (int d = 0; d < 32; d++) sk[r][d] *= sc;
    }
    __syncthreads();

    #pragma unroll 1
    for (int it = 0; it < 32; it++) {
        int s = tid + (it << 7);
        int i = s >> 6, j = s & 63;
        const float4* qv = (const float4*)sq[i];
        const float4* kv = (const float4*)sk[j];
        float acc = 0.0f;
        #pragma unroll
        for (int d = 0; d < 8; d++) {
            float4 a = qv[d], b = kv[d];
            acc += a.x * b.x + a.y * b.y + a.z * b.z + a.w * b.w;
        }
        acc += g_rpbias[(head << 12) + (i << 6) + j];
        if (sreg[i] != sreg[j]) acc -= 100.0f;
        sS[i][j] = acc;
    }
    __syncthreads();

    if (tid < 64) {
        int r = tid;
        float m = -1e30f;
        #pragma unroll 4
        for (int j = 0; j < 64; j++) m = fmaxf(m, sS[r][j]);
        float sum = 0.0f;
        #pragma unroll 4
        for (int j = 0; j < 64; j++) { float e = expf(sS[r][j] - m); sS[r][j] = e; sum += e; }
        float inv = 1.0f / sum;
        #pragma unroll 4
        for (int j = 0; j < 64; j++) sS[r][j] *= inv;
    }
    __syncthreads();

    #pragma unroll 1
    for (int it = 0; it < 16; it++) {
        int e = tid + (it << 7);
        int i = e >> 5, d = e & 31;
        float acc = 0.0f;
        #pragma unroll
        for (int j = 0; j < 64; j++) acc += sS[i][j] * sv[j][d];
        g_ao[(size_t)(t0 + i) * CCH + (head << 5) + d] = acc;
    }
}

// ---------------------------------------------------------------------------
// Tensor-core GEMM: out[M x NC] = A[M x K] @ W[NC x K]^T  (+ epilogue)
// BM=128, BN=64, BK=32, 256 threads (8 warps, 4x2), warp tile 32x32,
// mma.sync.aligned.m16n8k8 tf32, fp32 accumulate.
// ---------------------------------------------------------------------------
__device__ __forceinline__ unsigned f2tf32(float f) {
    unsigned r;
    asm("cvt.rna.tf32.f32 %0, %1;" : "=r"(r) : "f"(f));
    return r;
}

__device__ __forceinline__ void mma_tf32(float* c, const unsigned* a, const unsigned* b) {
    asm volatile(
        "mma.sync.aligned.m16n8k8.row.col.f32.tf32.tf32.f32 "
        "{%0,%1,%2,%3}, {%4,%5,%6,%7}, {%8,%9}, {%0,%1,%2,%3};"
        : "+f"(c[0]), "+f"(c[1]), "+f"(c[2]), "+f"(c[3])
        : "r"(a[0]), "r"(a[1]), "r"(a[2]), "r"(a[3]), "r"(b[0]), "r"(b[1]));
}

template <int MODE>
__global__ void __launch_bounds__(256) gemm_kernel(const float* __restrict__ W,
                                                   const float* __restrict__ bias,
                                                   const float* __restrict__ bias2,
                                                   const float* __restrict__ aux,
                                                   float* __restrict__ outext) {
    constexpr int K  = (MODE == 3) ? 768 : 192;
    constexpr int NK = K >> 5;

    const float* A = (MODE == 0 || MODE == 2) ? g_xw : (MODE == 1 ? g_ao : g_h);

    __shared__ __align__(16) float As[128][36];
    __shared__ __align__(16) float Bs[64][36];

    int tid = threadIdx.x;
    int m0 = blockIdx.y << 7;
    int o0 = blockIdx.x << 6;
    const float* Ab = A + (size_t)m0 * K;
    const float* Wb = W + (size_t)o0 * K;

    int ar = tid >> 3;            // 0..31
    int ac = (tid & 7) << 2;      // 0,4,...,28

    float4 pa[4], pb[2];
    #pragma unroll
    for (int p = 0; p < 4; p++)
        pa[p] = *(const float4*)&Ab[(size_t)(ar + (p << 5)) * K + ac];
    #pragma unroll
    for (int p = 0; p < 2; p++)
        pb[p] = *(const float4*)&Wb[(size_t)(ar + (p << 5)) * K + ac];

    int warp = tid >> 5;
    int lane = tid & 31;
    int wm = (warp & 3) << 5;     // warp M offset within block (4 warps)
    int wn = (warp >> 2) << 5;    // warp N offset within block (2 warps)
    int gq = lane >> 2;           // groupID 0..7
    int tg = lane & 3;            // threadID_in_group 0..3

    float acc[2][4][4];
    #pragma unroll
    for (int mt = 0; mt < 2; mt++)
        #pragma unroll
        for (int nt = 0; nt < 4; nt++)
            #pragma unroll
            for (int r = 0; r < 4; r++) acc[mt][nt][r] = 0.0f;

    #pragma unroll 1
    for (int kt = 0; kt < NK; kt++) {
        #pragma unroll
        for (int p = 0; p < 4; p++)
            *(float4*)&As[ar + (p << 5)][ac] = pa[p];
        #pragma unroll
        for (int p = 0; p < 2; p++)
            *(float4*)&Bs[ar + (p << 5)][ac] = pb[p];
        __syncthreads();
        if (kt + 1 < NK) {
            int k0 = (kt + 1) << 5;
            #pragma unroll
            for (int p = 0; p < 4; p++)
                pa[p] = *(const float4*)&Ab[(size_t)(ar + (p << 5)) * K + k0 + ac];
            #pragma unroll
            for (int p = 0; p < 2; p++)
                pb[p] = *(const float4*)&Wb[(size_t)(ar + (p << 5)) * K + k0 + ac];
        }
        #pragma unroll
        for (int ks = 0; ks < 4; ks++) {
            int k0 = ks << 3;
            unsigned afr[2][4], bfr[4][2];
            #pragma unroll
            for (int mt = 0; mt < 2; mt++) {
                int rb = wm + (mt << 4) + gq;
                afr[mt][0] = f2tf32(As[rb    ][k0 + tg    ]);
                afr[mt][1] = f2tf32(As[rb + 8][k0 + tg    ]);
                afr[mt][2] = f2tf32(As[rb    ][k0 + tg + 4]);
                afr[mt][3] = f2tf32(As[rb + 8][k0 + tg + 4]);
            }
            #pragma unroll
            for (int nt = 0; nt < 4; nt++) {
                int nb = wn + (nt << 3) + gq;
                bfr[nt][0] = f2tf32(Bs[nb][k0 + tg    ]);
                bfr[nt][1] = f2tf32(Bs[nb][k0 + tg + 4]);
            }
            #pragma unroll
            for (int mt = 0; mt < 2; mt++)
                #pragma unroll
                for (int nt = 0; nt < 4; nt++)
                    mma_tf32(acc[mt][nt], afr[mt], bfr[nt]);
        }
        __syncthreads();
    }

    // Epilogue: c-frag (row = gq / gq+8, col = 2*tg, 2*tg+1)
    #pragma unroll
    for (int mt = 0; mt < 2; mt++) {
        #pragma unroll
        for (int rr = 0; rr < 2; rr++) {
            int m = m0 + wm + (mt << 4) + gq + (rr << 3);
            // MODE 1 scatter coords (per row)
            int b_ = 0, h_ = 0, w_ = 0;
            if constexpr (MODE == 1) {
                int win = m >> 6, n = m & 63;
                b_ = win >> 8;
                int wi = win & 255;
                h_ = ((((wi >> 4) << 3) + (n >> 3)) + 4) & 127;
                w_ = ((((wi & 15) << 3) + (n & 7)) + 4) & 127;
            }
            #pragma unroll
            for (int nt = 0; nt < 4; nt++) {
                int o = o0 + wn + (nt << 3) + (tg << 1);
                float v0 = acc[mt][nt][(rr << 1)];
                float v1 = acc[mt][nt][(rr << 1) + 1];
                if constexpr (MODE == 0) {
                    if (o < 192) { v0 += bias[o]; v1 += bias[o + 1]; }
                    else if (o >= 384) { v0 += bias2[o - 384]; v1 += bias2[o - 383]; }
                    *(float2*)&g_qkv[(size_t)m * 576 + o] = make_float2(v0, v1);
                } else if constexpr (MODE == 1) {
                    v0 += bias[o];
                    v1 += bias[o + 1];
                    size_t hw = (size_t)(h_ << 7) + w_;
                    v0 += aux[(((size_t)b_ * CCH + o) << 14) + hw];
                    v1 += aux[(((size_t)b_ * CCH + o + 1) << 14) + hw];
                    *(float2*)&g_x1[(size_t)((b_ << 14) + hw) * CCH + o] = make_float2(v0, v1);
                } else if constexpr (MODE == 2) {
                    v0 += bias[o];
                    v1 += bias[o + 1];
                    v0 = 0.5f * v0 * (1.0f + erff(v0 * 0.70710678118654752f));
                    v1 = 0.5f * v1 * (1.0f + erff(v1 * 0.70710678118654752f));
                    *(float2*)&g_h[(size_t)m * HID + o] = make_float2(v0, v1);
                } else {
                    const float* x1r = g_x1 + (size_t)m * CCH;
                    v0 += bias[o] + x1r[o];
                    v1 += bias[o + 1] + x1r[o + 1];
                    int b = m >> 14, hw = m & 16383;
                    outext[(((size_t)b * CCH + o) << 14) + hw] = v0;
                    outext[(((size_t)b * CCH + o + 1) << 14) + hw] = v1;
                }
            }
        }
    }
}

// ---------------------------------------------------------------------------
extern "C" void kernel_launch(void* const* d_in, const int* in_sizes, int n_in,
                              void* d_out, int out_size) {
    const float* x        = (const float*)d_in[0];
    const float* norm1_w  = (const float*)d_in[1];
    const float* norm1_b  = (const float*)d_in[2];
    const float* qkv_w    = (const float*)d_in[3];
    const float* q_bias   = (const float*)d_in[4];
    const float* v_bias   = (const float*)d_in[5];
    const float* logit_sc = (const float*)d_in[6];
    const float* cpb_w1   = (const float*)d_in[7];
    const float* cpb_b1   = (const float*)d_in[8];
    const float* cpb_w2   = (const float*)d_in[9];
    const float* proj_w   = (const float*)d_in[10];
    const float* proj_b   = (const float*)d_in[11];
    const float* norm2_w  = (const float*)d_in[12];
    const float* norm2_b  = (const float*)d_in[13];
    const float* fc1_w    = (const float*)d_in[14];
    const float* fc1_b    = (const float*)d_in[15];
    const float* fc2_w    = (const float*)d_in[16];
    const float* fc2_b    = (const float*)d_in[17];
    float* out = (float*)d_out;

    cpb_table_kernel<<<225, 512>>>(cpb_w1, cpb_b1, cpb_w2);
    rpbias_kernel<<<96, 256>>>();
    ln1_kernel<<<TOK / 32, 192>>>(x, norm1_w, norm1_b);
    gemm_kernel<0><<<dim3(9, TOK / 128), 256>>>(qkv_w, q_bias, v_bias, nullptr, nullptr);
    attn_kernel<<<dim3(HEADS, NWIN), 128>>>(logit_sc);
    gemm_kernel<1><<<dim3(3, TOK / 128), 256>>>(proj_w, proj_b, nullptr, x, nullptr);
    ln2_kernel<<<TOK / 8, 256>>>(norm2_w, norm2_b);
    gemm_kernel<2><<<dim3(12, TOK / 128), 256>>>(fc1_w, fc1_b, nullptr, nullptr, nullptr);
    gemm_kernel<3><<<dim3(3, TOK / 128), 256>>>(fc2_w, fc2_b, nullptr, nullptr, out);
}